// round 1
// baseline (speedup 1.0000x reference)
#include <cuda_runtime.h>

// Problem constants (shapes fixed by the dataset)
#define cN   10000
#define cE   160000
#define cET  170000   // E + N self loops
#define cTE  65536

// ---------------- scratch (device globals; no allocation allowed) ----------------
__device__ float g_xg  [cN*384];   // fc1 out
__device__ float g_h1  [cN*384];   // xg @ gat1_w
__device__ float g_agg1[cN*384];   // gat1 aggregate
__device__ float g_hr1 [cN*384];   // relu(x + bn1)
__device__ float g_hmid[cN*256];   // fc5 out
__device__ float g_h2g [cN*256];   // hmid @ gat2_w
__device__ float g_agg2[cN*256];
__device__ float g_h2  [cN*256];   // relu(hmid + bn2)
__device__ float g_h3  [cN*256];   // fc2 out
__device__ float g_as1 [cN*8];
__device__ float g_ad1 [cN*8];
__device__ float g_as2 [cN];
__device__ float g_ad2 [cN];
__device__ int   g_deg [cN+1];
__device__ int   g_off [cN+1];
__device__ int   g_cur [cN];
__device__ int   g_csr [cET];
__device__ float g_bnsum[2*384 + 2*256];  // [sum1|sq1|sum2|sq2]

// ---------------- CSR build ----------------
__global__ void zero_k() {
    int i = blockIdx.x * blockDim.x + threadIdx.x;
    if (i <= cN) g_deg[i] = 0;
    if (i < 2*384 + 2*256) g_bnsum[i] = 0.f;
}

__global__ void hist_k(const int* __restrict__ ei) {
    int e = blockIdx.x * blockDim.x + threadIdx.x;
    if (e >= cET) return;
    int dst = (e < cE) ? ei[cE + e] : (e - cE);
    atomicAdd(&g_deg[dst], 1);
}

__global__ __launch_bounds__(1024) void scan_k() {
    __shared__ int s[1024];
    int tid = threadIdx.x;
    int carry = 0;
    for (int base = 0; base < cN; base += 1024) {
        int i = base + tid;
        int v = (i < cN) ? g_deg[i] : 0;
        s[tid] = v;
        __syncthreads();
        int x = v;
        #pragma unroll
        for (int d = 1; d < 1024; d <<= 1) {
            int add = (tid >= d) ? s[tid - d] : 0;
            __syncthreads();
            x += add;
            s[tid] = x;
            __syncthreads();
        }
        int total = s[1023];
        if (i < cN) { int ex = carry + x - v; g_off[i] = ex; g_cur[i] = ex; }
        carry += total;
        __syncthreads();
    }
    if (tid == 0) g_off[cN] = carry;
}

__global__ void scatter_k(const int* __restrict__ ei) {
    int e = blockIdx.x * blockDim.x + threadIdx.x;
    if (e >= cET) return;
    int src, dst;
    if (e < cE) { src = ei[e]; dst = ei[cE + e]; }
    else        { src = e - cE; dst = e - cE; }
    int pos = atomicAdd(&g_cur[dst], 1);
    g_csr[pos] = src;
}

// ---------------- SGEMM: C = A(MxK) @ B(KxN) + bias, row-major ----------------
// BM=128 BN=128 BK=8, 256 threads, 8x8 per-thread. N must be a multiple of 128,
// K a multiple of 8 (384/256 both ok). Row-guarded for M tail.
__global__ __launch_bounds__(256) void sgemm_k(
    const float* __restrict__ A, const float* __restrict__ B,
    const float* __restrict__ bias, float* __restrict__ C,
    int M, int N, int K)
{
    const int BM=128, BN=128, BK=8, TM=8, TN=8;
    __shared__ float As[BK][BM+4];
    __shared__ float Bs[BK][BN];
    int tid = threadIdx.x;
    int bm = blockIdx.y * BM, bn = blockIdx.x * BN;
    int arow = tid >> 1;
    int acol = (tid & 1) * 4;
    int brow = tid >> 5;
    int bcol = (tid & 31) * 4;
    int ty = tid >> 4, tx = tid & 15;
    bool arow_ok = (bm + arow) < M;
    float acc[TM][TN];
    #pragma unroll
    for (int i = 0; i < TM; i++)
        #pragma unroll
        for (int j = 0; j < TN; j++) acc[i][j] = 0.f;

    for (int k0 = 0; k0 < K; k0 += BK) {
        float4 av = make_float4(0.f, 0.f, 0.f, 0.f);
        if (arow_ok)
            av = *reinterpret_cast<const float4*>(A + (size_t)(bm + arow) * K + k0 + acol);
        As[acol+0][arow] = av.x; As[acol+1][arow] = av.y;
        As[acol+2][arow] = av.z; As[acol+3][arow] = av.w;
        float4 bv = *reinterpret_cast<const float4*>(B + (size_t)(k0 + brow) * N + bn + bcol);
        *reinterpret_cast<float4*>(&Bs[brow][bcol]) = bv;
        __syncthreads();
        #pragma unroll
        for (int kk = 0; kk < BK; kk++) {
            float a[TM], b[TN];
            #pragma unroll
            for (int i = 0; i < TM; i++) a[i] = As[kk][ty*TM + i];
            #pragma unroll
            for (int j = 0; j < TN; j++) b[j] = Bs[kk][tx*TN + j];
            #pragma unroll
            for (int i = 0; i < TM; i++)
                #pragma unroll
                for (int j = 0; j < TN; j++) acc[i][j] += a[i] * b[j];
        }
        __syncthreads();
    }
    #pragma unroll
    for (int i = 0; i < TM; i++) {
        int r = bm + ty*TM + i;
        if (r < M) {
            #pragma unroll
            for (int j = 0; j < TN; j++) {
                int cc = bn + tx*TN + j;
                float bv = bias ? bias[cc] : 0.f;
                C[(size_t)r * N + cc] = acc[i][j] + bv;
            }
        }
    }
}

// ---------------- attention coefficients: one warp per (node, head) ----------------
__global__ void coef_k(const float* __restrict__ h, const float* __restrict__ a_s,
                       const float* __restrict__ a_d, float* __restrict__ asrc,
                       float* __restrict__ adst, int n, int H, int C)
{
    int gw = (blockIdx.x * blockDim.x + threadIdx.x) >> 5;
    int lane = threadIdx.x & 31;
    if (gw >= n * H) return;
    int node = gw / H, hd = gw - node * H;
    const float* hp = h + (size_t)node * H * C + hd * C;
    const float* ws = a_s + hd * C;
    const float* wd = a_d + hd * C;
    float ss = 0.f, sd = 0.f;
    for (int c = lane; c < C; c += 32) {
        float v = hp[c];
        ss += v * ws[c];
        sd += v * wd[c];
    }
    #pragma unroll
    for (int o = 16; o; o >>= 1) {
        ss += __shfl_xor_sync(0xffffffffu, ss, o);
        sd += __shfl_xor_sync(0xffffffffu, sd, o);
    }
    if (lane == 0) { asrc[gw] = ss; adst[gw] = sd; }
}

// ---------------- GAT edge softmax + aggregation (online softmax, block per dst) --
template<int H, int C>
__global__ void gat_edge_k(const float* __restrict__ h,
                           const float* __restrict__ asrc,
                           const float* __restrict__ adst,
                           float* __restrict__ out)
{
    __shared__ float s_m[H], s_den[H], s_scale[H], s_w[H], s_ad[H];
    int dst = blockIdx.x;
    int tid = threadIdx.x;       // H*C threads
    int hd = tid / C;
    if (tid < H) { s_m[tid] = -1e30f; s_den[tid] = 0.f; s_ad[tid] = adst[dst*H + tid]; }
    int beg = g_off[dst], end = g_off[dst + 1];
    float acc = 0.f;
    __syncthreads();
    for (int p = beg; p < end; p++) {
        int src = g_csr[p];
        if (tid < H) {
            float e = asrc[src*H + tid] + s_ad[tid];
            e = (e > 0.f) ? e : 0.2f * e;           // leaky_relu 0.2
            float mo = s_m[tid];
            float mn = fmaxf(mo, e);
            float sc = __expf(mo - mn);
            float w  = __expf(e - mn);
            s_m[tid] = mn;
            s_den[tid] = s_den[tid] * sc + w;
            s_scale[tid] = sc;
            s_w[tid] = w;
        }
        __syncthreads();
        acc = acc * s_scale[hd] + s_w[hd] * h[(size_t)src * (H*C) + tid];
        __syncthreads();
    }
    out[(size_t)dst * (H*C) + tid] = acc / (s_den[hd] + 1e-16f);
}

// ---------------- BN column reduction ----------------
__global__ void bnred_k(const float* __restrict__ x, float* __restrict__ sums,
                        int n, int C)
{
    int c = threadIdx.x;   // blockDim == C
    float s = 0.f, q = 0.f;
    for (int r = blockIdx.x; r < n; r += gridDim.x) {
        float v = x[(size_t)r * C + c];
        s += v; q += v * v;
    }
    atomicAdd(&sums[c], s);
    atomicAdd(&sums[C + c], q);
}

// ---------------- fused residual + BN + ReLU ----------------
__global__ void fuse_k(const float* __restrict__ resid, const float* __restrict__ agg,
                       const float* __restrict__ sums, const float* __restrict__ gamma,
                       const float* __restrict__ beta, float* __restrict__ out,
                       int n, int C)
{
    int idx = blockIdx.x * blockDim.x + threadIdx.x;
    if (idx >= n * C) return;
    int c = idx % C;
    float inv_n = 1.f / (float)n;
    float mu  = sums[c] * inv_n;
    float var = sums[C + c] * inv_n - mu * mu;
    float is  = rsqrtf(var + 1e-5f);
    float v = resid[idx] + (agg[idx] - mu) * is * gamma[c] + beta[c];
    out[idx] = fmaxf(v, 0.f);
}

// ---------------- final: pair = h[a]*h[b]; out = pair @ fc4_w + fc4_b ----------------
__global__ __launch_bounds__(256) void final_k(const float* __restrict__ h3,
    const int* __restrict__ ei, const int* __restrict__ te,
    const float* __restrict__ w, const float* __restrict__ b,
    float* __restrict__ out)
{
    __shared__ float sw[256*7];
    __shared__ float sb[7];
    int tid = threadIdx.x;
    for (int i = tid; i < 256*7; i += 256) sw[i] = w[i];
    if (tid < 7) sb[tid] = b[tid];
    __syncthreads();
    int t = blockIdx.x * 8 + (tid >> 5);
    int lane = tid & 31;
    if (t >= cTE) return;
    int eid = te[t];
    int na = ei[eid], nb = ei[cE + eid];
    const float* ra = h3 + (size_t)na * 256;
    const float* rb = h3 + (size_t)nb * 256;
    float p0=0,p1=0,p2=0,p3=0,p4=0,p5=0,p6=0;
    for (int c = lane; c < 256; c += 32) {
        float v = ra[c] * rb[c];
        const float* wr = &sw[c*7];
        p0 += v*wr[0]; p1 += v*wr[1]; p2 += v*wr[2]; p3 += v*wr[3];
        p4 += v*wr[4]; p5 += v*wr[5]; p6 += v*wr[6];
    }
    #pragma unroll
    for (int o = 16; o; o >>= 1) {
        p0 += __shfl_xor_sync(0xffffffffu, p0, o);
        p1 += __shfl_xor_sync(0xffffffffu, p1, o);
        p2 += __shfl_xor_sync(0xffffffffu, p2, o);
        p3 += __shfl_xor_sync(0xffffffffu, p3, o);
        p4 += __shfl_xor_sync(0xffffffffu, p4, o);
        p5 += __shfl_xor_sync(0xffffffffu, p5, o);
        p6 += __shfl_xor_sync(0xffffffffu, p6, o);
    }
    if (lane == 0) {
        float* o7 = out + (size_t)t * 7;
        o7[0]=p0+sb[0]; o7[1]=p1+sb[1]; o7[2]=p2+sb[2]; o7[3]=p3+sb[3];
        o7[4]=p4+sb[4]; o7[5]=p5+sb[5]; o7[6]=p6+sb[6];
    }
}

// ---------------- launch ----------------
extern "C" void kernel_launch(void* const* d_in, const int* in_sizes, int n_in,
                              void* d_out, int out_size)
{
    const float* x      = (const float*)d_in[0];
    const int*   ei     = (const int*)  d_in[1];
    const int*   te     = (const int*)  d_in[2];
    const float* fc1_w  = (const float*)d_in[3];
    const float* fc1_b  = (const float*)d_in[4];
    const float* fc5_w  = (const float*)d_in[5];
    const float* fc5_b  = (const float*)d_in[6];
    const float* fc2_w  = (const float*)d_in[7];
    const float* fc2_b  = (const float*)d_in[8];
    const float* fc4_w  = (const float*)d_in[9];
    const float* fc4_b  = (const float*)d_in[10];
    const float* gat1_w = (const float*)d_in[11];
    const float* gat1_as= (const float*)d_in[12];
    const float* gat1_ad= (const float*)d_in[13];
    // d_in[14] gat1_b: exactly cancelled by BN mean subtraction
    const float* gat2_w = (const float*)d_in[15];
    const float* gat2_as= (const float*)d_in[16];
    const float* gat2_ad= (const float*)d_in[17];
    // d_in[18] gat2_b: cancelled by BN
    const float* bn1_g  = (const float*)d_in[19];
    const float* bn1_b  = (const float*)d_in[20];
    const float* bn2_g  = (const float*)d_in[21];
    const float* bn2_b  = (const float*)d_in[22];
    float* out = (float*)d_out;

    float *p_xg,*p_h1,*p_agg1,*p_hr1,*p_hmid,*p_h2g,*p_agg2,*p_h2,*p_h3;
    float *p_as1,*p_ad1,*p_as2,*p_ad2,*p_bns;
    cudaGetSymbolAddress((void**)&p_xg,   g_xg);
    cudaGetSymbolAddress((void**)&p_h1,   g_h1);
    cudaGetSymbolAddress((void**)&p_agg1, g_agg1);
    cudaGetSymbolAddress((void**)&p_hr1,  g_hr1);
    cudaGetSymbolAddress((void**)&p_hmid, g_hmid);
    cudaGetSymbolAddress((void**)&p_h2g,  g_h2g);
    cudaGetSymbolAddress((void**)&p_agg2, g_agg2);
    cudaGetSymbolAddress((void**)&p_h2,   g_h2);
    cudaGetSymbolAddress((void**)&p_h3,   g_h3);
    cudaGetSymbolAddress((void**)&p_as1,  g_as1);
    cudaGetSymbolAddress((void**)&p_ad1,  g_ad1);
    cudaGetSymbolAddress((void**)&p_as2,  g_as2);
    cudaGetSymbolAddress((void**)&p_ad2,  g_ad2);
    cudaGetSymbolAddress((void**)&p_bns,  g_bnsum);

    // CSR by destination (shared by both GAT layers)
    zero_k   <<<41, 256>>>();
    hist_k   <<<(cET + 255)/256, 256>>>(ei);
    scan_k   <<<1, 1024>>>();
    scatter_k<<<(cET + 255)/256, 256>>>(ei);

    // Layer 1 (384 channels, 8 heads x 48)
    sgemm_k<<<dim3(3, 79), 256>>>(x,    fc1_w,  fc1_b,  p_xg, cN, 384, 384);
    sgemm_k<<<dim3(3, 79), 256>>>(p_xg, gat1_w, nullptr, p_h1, cN, 384, 384);
    coef_k <<<(cN*8*32 + 255)/256, 256>>>(p_h1, gat1_as, gat1_ad, p_as1, p_ad1, cN, 8, 48);
    gat_edge_k<8,48><<<cN, 384>>>(p_h1, p_as1, p_ad1, p_agg1);
    bnred_k<<<128, 384>>>(p_agg1, p_bns, cN, 384);
    fuse_k <<<(cN*384 + 255)/256, 256>>>(x, p_agg1, p_bns, bn1_g, bn1_b, p_hr1, cN, 384);

    // Layer 2 (256 channels, 1 head)
    sgemm_k<<<dim3(2, 79), 256>>>(p_hr1,  fc5_w,  fc5_b,  p_hmid, cN, 256, 384);
    sgemm_k<<<dim3(2, 79), 256>>>(p_hmid, gat2_w, nullptr, p_h2g,  cN, 256, 256);
    coef_k <<<(cN*32 + 255)/256, 256>>>(p_h2g, gat2_as, gat2_ad, p_as2, p_ad2, cN, 1, 256);
    gat_edge_k<1,256><<<cN, 256>>>(p_h2g, p_as2, p_ad2, p_agg2);
    bnred_k<<<128, 256>>>(p_agg2, p_bns + 768, cN, 256);
    fuse_k <<<(cN*256 + 255)/256, 256>>>(p_hmid, p_agg2, p_bns + 768, bn2_g, bn2_b, p_h2, cN, 256);

    // Head
    sgemm_k<<<dim3(2, 79), 256>>>(p_h2, fc2_w, fc2_b, p_h3, cN, 256, 256);
    final_k<<<cTE/8, 256>>>(p_h3, ei, te, fc4_w, fc4_b, out);
}

// round 3
// speedup vs baseline: 1.8511x; 1.8511x over previous
#include <cuda_runtime.h>
#include <cuda_bf16.h>
#include <cstdint>

#define cN   10000
#define cE   160000
#define cET  170000   // E + N self loops
#define cTE  65536

// ======================= device scratch (no allocation allowed) ================
__device__ __align__(256) __nv_bfloat16 g_ah[cN*384], g_al[cN*384];
__device__ __align__(256) __nv_bfloat16 g_bh[cN*384], g_bl[cN*384];
__device__ __align__(256) __nv_bfloat16 g_w1h[384*384],  g_w1l[384*384];
__device__ __align__(256) __nv_bfloat16 g_wg1h[384*384], g_wg1l[384*384];
__device__ __align__(256) __nv_bfloat16 g_w5h[256*384],  g_w5l[256*384];
__device__ __align__(256) __nv_bfloat16 g_wg2h[256*256], g_wg2l[256*256];
__device__ __align__(256) __nv_bfloat16 g_w2h[256*256],  g_w2l[256*256];
__device__ float g_h1  [cN*384];
__device__ float g_agg1[cN*384];
__device__ float g_hmid[cN*256];
__device__ float g_h2g [cN*256];
__device__ float g_agg2[cN*256];
__device__ float g_h3  [cN*256];
__device__ float g_as1[cN*8], g_ad1[cN*8], g_as2[cN], g_ad2[cN];
__device__ float g_alpha[cET*8];
__device__ float g_den[cN*8];
__device__ int   g_deg[cN+1], g_off[cN+1], g_cur[cN], g_csr[cET];
__device__ float g_bnsum[2*384 + 2*256];

// ======================= small asm helpers =======================
__device__ __forceinline__ uint32_t smem_u32(const void* p) {
    uint32_t a;
    asm("{ .reg .u64 t; cvta.to.shared.u64 t, %1; cvt.u32.u64 %0, t; }" : "=r"(a) : "l"(p));
    return a;
}
__device__ __forceinline__ void cp_async16(uint32_t dst, const void* src, int szbytes) {
    asm volatile("cp.async.ca.shared.global [%0], [%1], 16, %2;"
                 :: "r"(dst), "l"(src), "r"(szbytes) : "memory");
}
__device__ __forceinline__ void cp_commit() { asm volatile("cp.async.commit_group;" ::: "memory"); }
__device__ __forceinline__ void ldm_x4(uint32_t a, uint32_t& r0, uint32_t& r1, uint32_t& r2, uint32_t& r3) {
    asm volatile("ldmatrix.sync.aligned.m8n8.x4.shared.b16 {%0,%1,%2,%3}, [%4];"
                 : "=r"(r0), "=r"(r1), "=r"(r2), "=r"(r3) : "r"(a));
}
__device__ __forceinline__ void mma_bf16(float& d0, float& d1, float& d2, float& d3,
                                         uint32_t a0, uint32_t a1, uint32_t a2, uint32_t a3,
                                         uint32_t b0, uint32_t b1) {
    asm volatile("mma.sync.aligned.m16n8k16.row.col.f32.bf16.bf16.f32 "
                 "{%0,%1,%2,%3}, {%4,%5,%6,%7}, {%8,%9}, {%0,%1,%2,%3};"
                 : "+f"(d0), "+f"(d1), "+f"(d2), "+f"(d3)
                 : "r"(a0), "r"(a1), "r"(a2), "r"(a3), "r"(b0), "r"(b1));
}

// ======================= CSR build =======================
__global__ void zero_k() {
    int i = blockIdx.x * blockDim.x + threadIdx.x;
    if (i <= cN) g_deg[i] = 0;
    if (i < 2*384 + 2*256) g_bnsum[i] = 0.f;
}
__global__ void hist_k(const int* __restrict__ ei) {
    int e = blockIdx.x * blockDim.x + threadIdx.x;
    if (e >= cET) return;
    int dst = (e < cE) ? ei[cE + e] : (e - cE);
    atomicAdd(&g_deg[dst], 1);
}
__global__ __launch_bounds__(1024) void scan_k() {
    __shared__ int s[1024];
    int tid = threadIdx.x;
    int carry = 0;
    for (int base = 0; base < cN; base += 1024) {
        int i = base + tid;
        int v = (i < cN) ? g_deg[i] : 0;
        s[tid] = v;
        __syncthreads();
        int x = v;
        #pragma unroll
        for (int d = 1; d < 1024; d <<= 1) {
            int add = (tid >= d) ? s[tid - d] : 0;
            __syncthreads();
            x += add;
            s[tid] = x;
            __syncthreads();
        }
        int total = s[1023];
        if (i < cN) { int ex = carry + x - v; g_off[i] = ex; g_cur[i] = ex; }
        carry += total;
        __syncthreads();
    }
    if (tid == 0) g_off[cN] = carry;
}
__global__ void scatter_k(const int* __restrict__ ei) {
    int e = blockIdx.x * blockDim.x + threadIdx.x;
    if (e >= cET) return;
    int src, dst;
    if (e < cE) { src = ei[e]; dst = ei[cE + e]; }
    else        { src = e - cE; dst = e - cE; }
    int pos = atomicAdd(&g_cur[dst], 1);
    g_csr[pos] = src;
}

// ======================= fp32 -> bf16 hi/lo conversions =======================
__device__ __forceinline__ void split_bf16(float v, __nv_bfloat16& h, __nv_bfloat16& l) {
    h = __float2bfloat16(v);
    l = __float2bfloat16(v - __bfloat162float(h));
}

__global__ void conva_k(const float* __restrict__ x, __nv_bfloat16* __restrict__ oh,
                        __nv_bfloat16* __restrict__ ol, int n) {
    int i = blockIdx.x * blockDim.x + threadIdx.x;
    if (i >= n) return;
    __nv_bfloat16 h, l; split_bf16(x[i], h, l);
    oh[i] = h; ol[i] = l;
}

// All 5 weights: fp32 KxN -> transposed NxK bf16 hi/lo
__global__ void convw_k(const float* __restrict__ w1, const float* __restrict__ wg1,
                        const float* __restrict__ w5, const float* __restrict__ wg2,
                        const float* __restrict__ w2) {
    int t = blockIdx.x * blockDim.x + threadIdx.x;
    if (t >= 524288) return;
    const float* W; __nv_bfloat16 *oh, *ol; int K, N, i;
    if      (t < 147456) { W = w1;  oh = g_w1h;  ol = g_w1l;  K = 384; N = 384; i = t; }
    else if (t < 294912) { W = wg1; oh = g_wg1h; ol = g_wg1l; K = 384; N = 384; i = t - 147456; }
    else if (t < 393216) { W = w5;  oh = g_w5h;  ol = g_w5l;  K = 384; N = 256; i = t - 294912; }
    else if (t < 458752) { W = wg2; oh = g_wg2h; ol = g_wg2l; K = 256; N = 256; i = t - 393216; }
    else                 { W = w2;  oh = g_w2h;  ol = g_w2l;  K = 256; N = 256; i = t - 458752; }
    int k = i % K, n = i / K;
    __nv_bfloat16 h, l; split_bf16(W[(size_t)k * N + n], h, l);
    oh[i] = h; ol[i] = l;
}

// ======================= bf16x3 tensor-core GEMM (mma.sync) =======================
// C(MxN) = A(MxK) @ W(KxN), W stored transposed (NxK). hi/lo split: hh + hl + lh.
// 128x128 CTA tile, 8 warps (4x2), warp tile 32x64, BK=32, 2-stage cp.async.
// SMEM rows padded: 32 bf16 data + 16B pad => 80B stride (conflict-free ldmatrix).
#define ROWB   80
#define ARRB   10240              // 128 rows * 80B per array
#define STAGEB (4*ARRB)           // Ah, Al, Bh, Bl
#define GSMEM  (2*STAGEB)         // 81920 B

__global__ __launch_bounds__(256) void gemm_k(
    const __nv_bfloat16* __restrict__ Ah, const __nv_bfloat16* __restrict__ Al,
    const __nv_bfloat16* __restrict__ Bh, const __nv_bfloat16* __restrict__ Bl,
    const float* __restrict__ bias, float* __restrict__ C,
    __nv_bfloat16* __restrict__ Oh, __nv_bfloat16* __restrict__ Ol,
    int M, int N, int K)
{
    extern __shared__ char smem[];
    const uint32_t sb = smem_u32(smem);
    const int tid = threadIdx.x, wid = tid >> 5, lane = tid & 31;
    const int bm = blockIdx.y * 128, bn = blockIdx.x * 128;
    const int wm = wid & 3, wn = wid >> 2;         // warp tile: rows wm*32, cols wn*64
    const int q = lane >> 3, r = lane & 7;
    const uint32_t partA = (uint32_t)(((q & 1) * 8 + r) * ROWB + (q >> 1) * 16);
    const uint32_t partB = (uint32_t)(((q >> 1) * 8 + r) * ROWB + (q & 1) * 16);

    float acc[2][8][4];
    #pragma unroll
    for (int i = 0; i < 2; i++)
        #pragma unroll
        for (int j = 0; j < 8; j++)
            #pragma unroll
            for (int v = 0; v < 4; v++) acc[i][j][v] = 0.f;

    const int KT = K >> 5;

    // stage loader: 4 arrays x 512 16B chunks
    auto load_stage = [&](int s, int k0) {
        uint32_t base = sb + (uint32_t)s * STAGEB;
        #pragma unroll
        for (int u2 = 0; u2 < 2; u2++) {
            int u = tid + u2 * 256;                 // 0..511
            int row = u >> 2, c = u & 3;
            int gra = bm + row;
            const __nv_bfloat16* pa = Ah + (size_t)gra * K + k0 + c * 8;
            const __nv_bfloat16* pl = Al + (size_t)gra * K + k0 + c * 8;
            int sza = (gra < M) ? 16 : 0;
            uint32_t d = base + (uint32_t)(row * ROWB + c * 16);
            cp_async16(d,            pa, sza);
            cp_async16(d + ARRB,     pl, sza);
            int grb = bn + row;
            const __nv_bfloat16* pb = Bh + (size_t)grb * K + k0 + c * 8;
            const __nv_bfloat16* pq = Bl + (size_t)grb * K + k0 + c * 8;
            int szb = (grb < N) ? 16 : 0;
            cp_async16(d + 2*ARRB,   pb, szb);
            cp_async16(d + 3*ARRB,   pq, szb);
        }
    };

    load_stage(0, 0);
    cp_commit();

    for (int kt = 0; kt < KT; kt++) {
        if (kt + 1 < KT) { load_stage((kt + 1) & 1, (kt + 1) << 5); cp_commit(); }
        if (kt + 1 < KT) asm volatile("cp.async.wait_group 1;" ::: "memory");
        else             asm volatile("cp.async.wait_group 0;" ::: "memory");
        __syncthreads();

        uint32_t stg = sb + (uint32_t)(kt & 1) * STAGEB;
        #pragma unroll
        for (int ks = 0; ks < 2; ks++) {
            uint32_t koff = (uint32_t)(ks * 32);
            // A fragments (2 m16 frags, hi+lo)
            uint32_t ah[2][4], al[2][4];
            #pragma unroll
            for (int mf = 0; mf < 2; mf++) {
                uint32_t ao = stg + (uint32_t)((wm * 32 + mf * 16) * ROWB) + koff + partA;
                ldm_x4(ao,        ah[mf][0], ah[mf][1], ah[mf][2], ah[mf][3]);
                ldm_x4(ao + ARRB, al[mf][0], al[mf][1], al[mf][2], al[mf][3]);
            }
            // B: 4 n16 groups (8 n8 frags), hi+lo
            #pragma unroll
            for (int jp = 0; jp < 4; jp++) {
                uint32_t bo = stg + 2*ARRB + (uint32_t)((wn * 64 + jp * 16) * ROWB) + koff + partB;
                uint32_t bh0, bh1, bh2, bh3, bl0, bl1, bl2, bl3;
                ldm_x4(bo,        bh0, bh1, bh2, bh3);
                ldm_x4(bo + ARRB, bl0, bl1, bl2, bl3);
                #pragma unroll
                for (int mf = 0; mf < 2; mf++) {
                    float* c0 = acc[mf][2*jp];
                    float* c1 = acc[mf][2*jp + 1];
                    mma_bf16(c0[0],c0[1],c0[2],c0[3], ah[mf][0],ah[mf][1],ah[mf][2],ah[mf][3], bh0,bh1);
                    mma_bf16(c1[0],c1[1],c1[2],c1[3], ah[mf][0],ah[mf][1],ah[mf][2],ah[mf][3], bh2,bh3);
                    mma_bf16(c0[0],c0[1],c0[2],c0[3], ah[mf][0],ah[mf][1],ah[mf][2],ah[mf][3], bl0,bl1);
                    mma_bf16(c1[0],c1[1],c1[2],c1[3], ah[mf][0],ah[mf][1],ah[mf][2],ah[mf][3], bl2,bl3);
                    mma_bf16(c0[0],c0[1],c0[2],c0[3], al[mf][0],al[mf][1],al[mf][2],al[mf][3], bh0,bh1);
                    mma_bf16(c1[0],c1[1],c1[2],c1[3], al[mf][0],al[mf][1],al[mf][2],al[mf][3], bh2,bh3);
                }
            }
        }
        __syncthreads();
    }

    // epilogue: bias + fp32 store + optional bf16 hi/lo split store
    #pragma unroll
    for (int mf = 0; mf < 2; mf++) {
        int row0 = bm + wm * 32 + mf * 16 + (lane >> 2);
        #pragma unroll
        for (int nf = 0; nf < 8; nf++) {
            int col = bn + wn * 64 + nf * 8 + (lane & 3) * 2;
            float b0 = bias ? bias[col] : 0.f;
            float b1 = bias ? bias[col + 1] : 0.f;
            float v00 = acc[mf][nf][0] + b0, v01 = acc[mf][nf][1] + b1;
            float v10 = acc[mf][nf][2] + b0, v11 = acc[mf][nf][3] + b1;
            if (row0 < M) {
                if (C) *reinterpret_cast<float2*>(C + (size_t)row0 * N + col) = make_float2(v00, v01);
                if (Oh) {
                    __nv_bfloat16 h0, l0, h1, l1;
                    split_bf16(v00, h0, l0); split_bf16(v01, h1, l1);
                    __nv_bfloat162 hh; hh.x = h0; hh.y = h1;
                    __nv_bfloat162 ll; ll.x = l0; ll.y = l1;
                    *reinterpret_cast<__nv_bfloat162*>(Oh + (size_t)row0 * N + col) = hh;
                    *reinterpret_cast<__nv_bfloat162*>(Ol + (size_t)row0 * N + col) = ll;
                }
            }
            if (row0 + 8 < M) {
                if (C) *reinterpret_cast<float2*>(C + (size_t)(row0 + 8) * N + col) = make_float2(v10, v11);
                if (Oh) {
                    __nv_bfloat16 h0, l0, h1, l1;
                    split_bf16(v10, h0, l0); split_bf16(v11, h1, l1);
                    __nv_bfloat162 hh; hh.x = h0; hh.y = h1;
                    __nv_bfloat162 ll; ll.x = l0; ll.y = l1;
                    *reinterpret_cast<__nv_bfloat162*>(Oh + (size_t)(row0 + 8) * N + col) = hh;
                    *reinterpret_cast<__nv_bfloat162*>(Ol + (size_t)(row0 + 8) * N + col) = ll;
                }
            }
        }
    }
}

// ======================= attention coefficients =======================
__global__ void coef_k(const float* __restrict__ h, const float* __restrict__ a_s,
                       const float* __restrict__ a_d, float* __restrict__ asrc,
                       float* __restrict__ adst, int n, int H, int C)
{
    int gw = (blockIdx.x * blockDim.x + threadIdx.x) >> 5;
    int lane = threadIdx.x & 31;
    if (gw >= n * H) return;
    int node = gw / H, hd = gw - node * H;
    const float* hp = h + (size_t)node * H * C + hd * C;
    const float* ws = a_s + hd * C;
    const float* wd = a_d + hd * C;
    float ss = 0.f, sd = 0.f;
    for (int c = lane; c < C; c += 32) {
        float v = hp[c];
        ss += v * ws[c]; sd += v * wd[c];
    }
    #pragma unroll
    for (int o = 16; o; o >>= 1) {
        ss += __shfl_xor_sync(0xffffffffu, ss, o);
        sd += __shfl_xor_sync(0xffffffffu, sd, o);
    }
    if (lane == 0) { asrc[gw] = ss; adst[gw] = sd; }
}

// ======================= softmax norm (warp per (dst,head)) =======================
template<int H>
__global__ void attn_k(const float* __restrict__ asrc, const float* __restrict__ adst)
{
    int wid = threadIdx.x >> 5, lane = threadIdx.x & 31;
    int gw = blockIdx.x * 8 + wid;
    int dst = gw / H, hd = gw - dst * H;
    if (dst >= cN) return;
    int beg = g_off[dst], end = g_off[dst + 1];
    float ad = adst[dst * H + hd];
    float m = -1e30f;
    for (int p = beg + lane; p < end; p += 32) {
        int s = g_csr[p];
        float e = asrc[s * H + hd] + ad;
        e = (e > 0.f) ? e : 0.2f * e;
        m = fmaxf(m, e);
    }
    #pragma unroll
    for (int o = 16; o; o >>= 1) m = fmaxf(m, __shfl_xor_sync(0xffffffffu, m, o));
    float den = 0.f;
    for (int p = beg + lane; p < end; p += 32) {
        int s = g_csr[p];
        float e = asrc[s * H + hd] + ad;
        e = (e > 0.f) ? e : 0.2f * e;
        float w = __expf(e - m);
        den += w;
        g_alpha[(size_t)p * H + hd] = w;
    }
    #pragma unroll
    for (int o = 16; o; o >>= 1) den += __shfl_xor_sync(0xffffffffu, den, o);
    if (lane == 0) g_den[dst * H + hd] = den + 1e-16f;
}

// ======================= SpMM aggregation (block per dst, no barriers) =============
template<int H, int C>
__global__ void spmm_k(const float* __restrict__ h, float* __restrict__ out)
{
    const int HC = H * C;
    int dst = blockIdx.x, tid = threadIdx.x;
    int hd = tid / C;
    int beg = g_off[dst], end = g_off[dst + 1];
    float inv = 1.f / g_den[dst * H + hd];
    float acc = 0.f;
    int p = beg;
    for (; p + 2 <= end; p += 2) {
        int s0 = g_csr[p], s1 = g_csr[p + 1];
        float w0 = g_alpha[(size_t)p * H + hd];
        float w1 = g_alpha[(size_t)(p + 1) * H + hd];
        float v0 = h[(size_t)s0 * HC + tid];
        float v1 = h[(size_t)s1 * HC + tid];
        acc += w0 * v0 + w1 * v1;
    }
    if (p < end) {
        int s0 = g_csr[p];
        acc += g_alpha[(size_t)p * H + hd] * h[(size_t)s0 * HC + tid];
    }
    out[(size_t)dst * HC + tid] = acc * inv;
}

// ======================= BN reduction + fused residual/BN/ReLU =======================
__global__ void bnred_k(const float* __restrict__ x, float* __restrict__ sums, int n, int C)
{
    int c = threadIdx.x;
    float s = 0.f, q = 0.f;
    for (int r = blockIdx.x; r < n; r += gridDim.x) {
        float v = x[(size_t)r * C + c];
        s += v; q += v * v;
    }
    atomicAdd(&sums[c], s);
    atomicAdd(&sums[C + c], q);
}

__global__ void fuse_k(const float* __restrict__ resid, const float* __restrict__ agg,
                       const float* __restrict__ sums, const float* __restrict__ gamma,
                       const float* __restrict__ beta, float* __restrict__ outf,
                       __nv_bfloat16* __restrict__ oh, __nv_bfloat16* __restrict__ ol,
                       int n, int C)
{
    int idx = blockIdx.x * blockDim.x + threadIdx.x;
    if (idx >= n * C) return;
    int c = idx % C;
    float inv_n = 1.f / (float)n;
    float mu  = sums[c] * inv_n;
    float var = sums[C + c] * inv_n - mu * mu;
    float is  = rsqrtf(var + 1e-5f);
    float v = resid[idx] + (agg[idx] - mu) * is * gamma[c] + beta[c];
    v = fmaxf(v, 0.f);
    if (outf) outf[idx] = v;
    __nv_bfloat16 h, l; split_bf16(v, h, l);
    oh[idx] = h; ol[idx] = l;
}

// ======================= final head =======================
__global__ __launch_bounds__(256) void final_k(const float* __restrict__ h3,
    const int* __restrict__ ei, const int* __restrict__ te,
    const float* __restrict__ w, const float* __restrict__ b,
    float* __restrict__ out)
{
    __shared__ float sw[256*7];
    __shared__ float sb[7];
    int tid = threadIdx.x;
    for (int i = tid; i < 256*7; i += 256) sw[i] = w[i];
    if (tid < 7) sb[tid] = b[tid];
    __syncthreads();
    int t = blockIdx.x * 8 + (tid >> 5);
    int lane = tid & 31;
    if (t >= cTE) return;
    int eid = te[t];
    int na = ei[eid], nb = ei[cE + eid];
    const float* ra = h3 + (size_t)na * 256;
    const float* rb = h3 + (size_t)nb * 256;
    float p0=0,p1=0,p2=0,p3=0,p4=0,p5=0,p6=0;
    for (int c = lane; c < 256; c += 32) {
        float v = ra[c] * rb[c];
        const float* wr = &sw[c*7];
        p0 += v*wr[0]; p1 += v*wr[1]; p2 += v*wr[2]; p3 += v*wr[3];
        p4 += v*wr[4]; p5 += v*wr[5]; p6 += v*wr[6];
    }
    #pragma unroll
    for (int o = 16; o; o >>= 1) {
        p0 += __shfl_xor_sync(0xffffffffu, p0, o);
        p1 += __shfl_xor_sync(0xffffffffu, p1, o);
        p2 += __shfl_xor_sync(0xffffffffu, p2, o);
        p3 += __shfl_xor_sync(0xffffffffu, p3, o);
        p4 += __shfl_xor_sync(0xffffffffu, p4, o);
        p5 += __shfl_xor_sync(0xffffffffu, p5, o);
        p6 += __shfl_xor_sync(0xffffffffu, p6, o);
    }
    if (lane == 0) {
        float* o7 = out + (size_t)t * 7;
        o7[0]=p0+sb[0]; o7[1]=p1+sb[1]; o7[2]=p2+sb[2]; o7[3]=p3+sb[3];
        o7[4]=p4+sb[4]; o7[5]=p5+sb[5]; o7[6]=p6+sb[6];
    }
}

// ======================= launch =======================
extern "C" void kernel_launch(void* const* d_in, const int* in_sizes, int n_in,
                              void* d_out, int out_size)
{
    const float* x      = (const float*)d_in[0];
    const int*   ei     = (const int*)  d_in[1];
    const int*   te     = (const int*)  d_in[2];
    const float* fc1_w  = (const float*)d_in[3];
    const float* fc1_b  = (const float*)d_in[4];
    const float* fc5_w  = (const float*)d_in[5];
    const float* fc5_b  = (const float*)d_in[6];
    const float* fc2_w  = (const float*)d_in[7];
    const float* fc2_b  = (const float*)d_in[8];
    const float* fc4_w  = (const float*)d_in[9];
    const float* fc4_b  = (const float*)d_in[10];
    const float* gat1_w = (const float*)d_in[11];
    const float* gat1_as= (const float*)d_in[12];
    const float* gat1_ad= (const float*)d_in[13];
    // d_in[14] gat1_b cancelled by BN mean subtraction
    const float* gat2_w = (const float*)d_in[15];
    const float* gat2_as= (const float*)d_in[16];
    const float* gat2_ad= (const float*)d_in[17];
    // d_in[18] gat2_b cancelled by BN
    const float* bn1_g  = (const float*)d_in[19];
    const float* bn1_b  = (const float*)d_in[20];
    const float* bn2_g  = (const float*)d_in[21];
    const float* bn2_b  = (const float*)d_in[22];
    float* out = (float*)d_out;

    cudaFuncSetAttribute(gemm_k, cudaFuncAttributeMaxDynamicSharedMemorySize, GSMEM);

    float *p_h1,*p_agg1,*p_hmid,*p_h2g,*p_agg2,*p_h3;
    float *p_as1,*p_ad1,*p_as2,*p_ad2,*p_bns;
    __nv_bfloat16 *p_ah,*p_al,*p_bh,*p_bl;
    __nv_bfloat16 *p_w1h,*p_w1l,*p_wg1h,*p_wg1l,*p_w5h,*p_w5l,*p_wg2h,*p_wg2l,*p_w2h,*p_w2l;
    cudaGetSymbolAddress((void**)&p_h1,   g_h1);
    cudaGetSymbolAddress((void**)&p_agg1, g_agg1);
    cudaGetSymbolAddress((void**)&p_hmid, g_hmid);
    cudaGetSymbolAddress((void**)&p_h2g,  g_h2g);
    cudaGetSymbolAddress((void**)&p_agg2, g_agg2);
    cudaGetSymbolAddress((void**)&p_h3,   g_h3);
    cudaGetSymbolAddress((void**)&p_as1,  g_as1);
    cudaGetSymbolAddress((void**)&p_ad1,  g_ad1);
    cudaGetSymbolAddress((void**)&p_as2,  g_as2);
    cudaGetSymbolAddress((void**)&p_ad2,  g_ad2);
    cudaGetSymbolAddress((void**)&p_bns,  g_bnsum);
    cudaGetSymbolAddress((void**)&p_ah,   g_ah);
    cudaGetSymbolAddress((void**)&p_al,   g_al);
    cudaGetSymbolAddress((void**)&p_bh,   g_bh);
    cudaGetSymbolAddress((void**)&p_bl,   g_bl);
    cudaGetSymbolAddress((void**)&p_w1h,  g_w1h);   cudaGetSymbolAddress((void**)&p_w1l,  g_w1l);
    cudaGetSymbolAddress((void**)&p_wg1h, g_wg1h);  cudaGetSymbolAddress((void**)&p_wg1l, g_wg1l);
    cudaGetSymbolAddress((void**)&p_w5h,  g_w5h);   cudaGetSymbolAddress((void**)&p_w5l,  g_w5l);
    cudaGetSymbolAddress((void**)&p_wg2h, g_wg2h);  cudaGetSymbolAddress((void**)&p_wg2l, g_wg2l);
    cudaGetSymbolAddress((void**)&p_w2h,  g_w2h);   cudaGetSymbolAddress((void**)&p_w2l,  g_w2l);

    // CSR by destination + zero accumulators
    zero_k   <<<41, 256>>>();
    hist_k   <<<(cET + 255)/256, 256>>>(ei);
    scan_k   <<<1, 1024>>>();
    scatter_k<<<(cET + 255)/256, 256>>>(ei);

    // weight + input conversions
    convw_k<<<2048, 256>>>(fc1_w, gat1_w, fc5_w, gat2_w, fc2_w);
    conva_k<<<(cN*384 + 255)/256, 256>>>(x, p_ah, p_al, cN*384);

    // Layer 1 (384ch, 8 heads x 48)
    gemm_k<<<dim3(3, 79), 256, GSMEM>>>(p_ah, p_al, p_w1h, p_w1l, fc1_b,
                                        nullptr, p_bh, p_bl, cN, 384, 384);
    gemm_k<<<dim3(3, 79), 256, GSMEM>>>(p_bh, p_bl, p_wg1h, p_wg1l, nullptr,
                                        p_h1, nullptr, nullptr, cN, 384, 384);
    coef_k<<<(cN*8*32 + 255)/256, 256>>>(p_h1, gat1_as, gat1_ad, p_as1, p_ad1, cN, 8, 48);
    attn_k<8><<<cN, 256>>>(p_as1, p_ad1);
    spmm_k<8,48><<<cN, 384>>>(p_h1, p_agg1);
    bnred_k<<<128, 384>>>(p_agg1, p_bns, cN, 384);
    fuse_k<<<(cN*384 + 255)/256, 256>>>(x, p_agg1, p_bns, bn1_g, bn1_b,
                                        nullptr, p_ah, p_al, cN, 384);

    // Layer 2 (256ch, 1 head)
    gemm_k<<<dim3(2, 79), 256, GSMEM>>>(p_ah, p_al, p_w5h, p_w5l, fc5_b,
                                        p_hmid, p_bh, p_bl, cN, 256, 384);
    gemm_k<<<dim3(2, 79), 256, GSMEM>>>(p_bh, p_bl, p_wg2h, p_wg2l, nullptr,
                                        p_h2g, nullptr, nullptr, cN, 256, 256);
    coef_k<<<(cN*32 + 255)/256, 256>>>(p_h2g, gat2_as, gat2_ad, p_as2, p_ad2, cN, 1, 256);
    attn_k<1><<<cN/8, 256>>>(p_as2, p_ad2);
    spmm_k<1,256><<<cN, 256>>>(p_h2g, p_agg2);
    bnred_k<<<128, 256>>>(p_agg2, p_bns + 768, cN, 256);
    fuse_k<<<(cN*256 + 255)/256, 256>>>(p_hmid, p_agg2, p_bns + 768, bn2_g, bn2_b,
                                        nullptr, p_ah, p_al, cN, 256);

    // Head
    gemm_k<<<dim3(2, 79), 256, GSMEM>>>(p_ah, p_al, p_w2h, p_w2l, fc2_b,
                                        p_h3, nullptr, nullptr, cN, 256, 256);
    final_k<<<cTE/8, 256>>>(p_h3, ei, te, fc4_w, fc4_b, out);
}